// round 7
// baseline (speedup 1.0000x reference)
#include <cuda_runtime.h>
#include <cuda_fp16.h>
#include <cstdint>
#include <math.h>

// ---------------------------------------------------------------------------
// Problem constants
// ---------------------------------------------------------------------------
namespace {
constexpr int Hh   = 16;
constexpr int Ww   = 21;
constexpr int HW   = Hh * Ww;        // 336
constexpr int CIN  = 256;
constexpr int COUT = 1024;           // 4*F
constexpr int Tt   = 16;
constexpr int Bb   = 4;
constexpr int Ff   = 256;
constexpr int KTOT = 25 * CIN;       // 6400

constexpr size_t SEQ_ELEMS   = (size_t)Bb * Tt * HW * Ff;      // 5,505,024
constexpr size_t STATE_ELEMS = (size_t)Bb * HW * Ff;           // 344,064
constexpr size_t XG_ELEMS    = (size_t)Bb * Tt * HW * COUT;    // 22,020,096
constexpr size_t XG2_ELEMS   = (size_t)Bb * HW * COUT;         // 1,376,256
constexpr size_t W_ELEMS     = (size_t)KTOT * COUT;            // 6,553,600

constexpr float LO_SCALE   = 2048.0f;          // exact power of two
constexpr float LO_INV     = 1.0f / 2048.0f;

// conv tiling
constexpr int NCHUNK = KTOT / 64;            // 100 chunks of k=64
constexpr int MT     = 128;                  // CTA pixels
constexpr int NT     = 64;                   // CTA cout
constexpr int SROW_B = 144;                  // padded row stride (bytes)

constexpr int A_T_B   = MT * SROW_B;         // 18432
constexpr int B_T_B   = NT * SROW_B;         // 9216
constexpr int ALO_OFF = A_T_B;               // 18432
constexpr int BHI_OFF = 2 * A_T_B;           // 36864
constexpr int BLO_OFF = 2 * A_T_B + B_T_B;   // 46080
constexpr int BUF_B   = 2 * A_T_B + 2 * B_T_B; // 55296 per stage
constexpr int SMEM_TOT = 2 * BUF_B;            // 110592 (double buffer)
}

// ---------------------------------------------------------------------------
// Scratch (device globals — no allocation allowed)
// ---------------------------------------------------------------------------
__device__ float  g_xg[XG_ELEMS];
__device__ float  g_xg2[XG2_ELEMS];
__device__ float  g_seq1[SEQ_ELEMS];
__device__ float  g_seq2[SEQ_ELEMS];
__device__ float  g_c[STATE_ELEMS];
__device__ float2 g_stats[Bb * Ff];

__device__ __align__(16) __half g_ah[SEQ_ELEMS];      // conv input hi
__device__ __align__(16) __half g_al[SEQ_ELEMS];      // conv input lo * 2048
__device__ __align__(16) __half g_hh[SEQ_ELEMS];      // hidden hi
__device__ __align__(16) __half g_hl[SEQ_ELEMS];      // hidden lo * 2048
__device__ __align__(16) __half g_whi[4][W_ELEMS];    // weights [co][k] hi
__device__ __align__(16) __half g_wlo[4][W_ELEMS];    // weights [co][k] lo * 2048

// ---------------------------------------------------------------------------
// PTX helpers (portable to plain sm_103)
// ---------------------------------------------------------------------------
__device__ __forceinline__ uint32_t smem_u32(const void* p) {
    uint32_t a;
    asm("{ .reg .u64 t; cvta.to.shared.u64 t, %1; cvt.u32.u64 %0, t; }" : "=r"(a) : "l"(p));
    return a;
}
__device__ __forceinline__ void cp16(uint32_t dst, const void* src, uint32_t srcsz) {
    asm volatile("cp.async.cg.shared.global [%0], [%1], 16, %2;"
                 :: "r"(dst), "l"(src), "r"(srcsz) : "memory");
}
#define CP_COMMIT() asm volatile("cp.async.commit_group;" ::: "memory")
#define CP_WAIT1()  asm volatile("cp.async.wait_group 1;" ::: "memory")
#define CP_WAIT0()  asm volatile("cp.async.wait_group 0;" ::: "memory")

__device__ __forceinline__ void ldsm4(uint32_t* r, uint32_t addr) {
    asm volatile("ldmatrix.sync.aligned.m8n8.x4.shared.b16 {%0,%1,%2,%3}, [%4];"
                 : "=r"(r[0]), "=r"(r[1]), "=r"(r[2]), "=r"(r[3]) : "r"(addr));
}
__device__ __forceinline__ void ldsm2(uint32_t* r, uint32_t addr) {
    asm volatile("ldmatrix.sync.aligned.m8n8.x2.shared.b16 {%0,%1}, [%2];"
                 : "=r"(r[0]), "=r"(r[1]) : "r"(addr));
}
// hi*hi term: fp32 accumulate
__device__ __forceinline__ void mma_f32(float* d, const uint32_t* a, const uint32_t* b)
{
    asm volatile(
        "mma.sync.aligned.m16n8k16.row.col.f32.f16.f16.f32 "
        "{%0,%1,%2,%3}, {%4,%5,%6,%7}, {%8,%9}, {%0,%1,%2,%3};"
        : "+f"(d[0]), "+f"(d[1]), "+f"(d[2]), "+f"(d[3])
        : "r"(a[0]), "r"(a[1]), "r"(a[2]), "r"(a[3]), "r"(b[0]), "r"(b[1]));
}
// cross terms: fp16 accumulate (operands pre-scaled by 2048 keep products normal)
__device__ __forceinline__ void mma_f16(uint32_t* d, const uint32_t* a, const uint32_t* b)
{
    asm volatile(
        "mma.sync.aligned.m16n8k16.row.col.f16.f16.f16.f16 "
        "{%0,%1}, {%2,%3,%4,%5}, {%6,%7}, {%0,%1};"
        : "+r"(d[0]), "+r"(d[1])
        : "r"(a[0]), "r"(a[1]), "r"(a[2]), "r"(a[3]), "r"(b[0]), "r"(b[1]));
}

// ---------------------------------------------------------------------------
// Implicit-GEMM 5x5 SAME conv, 256 -> 1024, fp16 3-term split:
//   out = Ahi*Bhi (f32 acc)  +  (Ahi*Blo' + Alo'*Bhi) (f16 acc) / 2048
// grid = (ceil(Mtot/128), 16, Z). Z==1: full K + bias. Z==2: split-K halves.
// ---------------------------------------------------------------------------
__global__ __launch_bounds__(256, 2) void conv_mma(
    const __half* __restrict__ a_hi, const __half* __restrict__ a_lo,
    size_t a_img_stride,
    const __half* __restrict__ w_hi, const __half* __restrict__ w_lo,
    const float* __restrict__ bias,
    float* __restrict__ out, size_t out_img_stride,
    float* __restrict__ out2, size_t out2_img_stride,
    int Mtot)
{
    extern __shared__ __align__(16) char sm[];
    const uint32_t smb = smem_u32(sm);

    const int tid  = threadIdx.x;
    const int lane = tid & 31;
    const int wid  = tid >> 5;
    const int m0   = blockIdx.x * MT;
    const int co0  = blockIdx.y * NT;

    int cbeg = 0, cend = NCHUNK;
    float* dst = out;
    size_t dstride = out_img_stride;
    bool accum = false;
    const float* bs = bias;
    if (gridDim.z == 2) {
        bs = nullptr;
        if (blockIdx.z == 0) { cend = NCHUNK / 2; accum = true; }
        else { cbeg = NCHUNK / 2; dst = out2; dstride = out2_img_stride; }
    }

    // ---- staging geometry
    const int arow  = tid >> 1;
    const int ahalf = tid & 1;
    int pc = m0 + arow; if (pc >= Mtot) pc = Mtot - 1;
    const int img = pc / HW;
    const int rm  = pc - img * HW;
    const int py  = rm / Ww;
    const int px  = rm - py * Ww;
    const __half* aimg_hi = a_hi + (size_t)img * a_img_stride;
    const __half* aimg_lo = a_lo + (size_t)img * a_img_stride;

    const int brow = tid >> 2;
    const int bq   = tid & 3;
    const __half* wrow_hi = w_hi + (size_t)(co0 + brow) * KTOT;
    const __half* wrow_lo = w_lo + (size_t)(co0 + brow) * KTOT;

    const uint32_t da0 = smb + arow * SROW_B + (ahalf << 6);
    const uint32_t db0 = smb + BHI_OFF + brow * SROW_B + (bq << 5);

    auto stage = [&](int c, int buf) {
        const uint32_t bo = (uint32_t)buf * BUF_B;
        const int tp  = c >> 2;
        const int ci0 = (c & 3) << 6;
        const int dy  = tp / 5;
        const int dx  = tp - dy * 5;
        const int gy  = py + dy - 2;
        const int gx  = px + dx - 2;
        const bool inb = (gy >= 0 && gy < Hh && gx >= 0 && gx < Ww);
        const uint32_t sz = inb ? 16u : 0u;
        const size_t off = inb ? ((((size_t)(gy * Ww + gx)) << 8) + ci0 + (ahalf << 5)) : 0;
        const char* sh = (const char*)(aimg_hi + off);
        const char* sl = (const char*)(aimg_lo + off);
        const uint32_t da = da0 + bo;
#pragma unroll
        for (int q = 0; q < 4; q++) {
            cp16(da + q * 16,           sh + q * 16, sz);
            cp16(da + ALO_OFF + q * 16, sl + q * 16, sz);
        }
        const char* wh = (const char*)(wrow_hi + (c << 6) + (bq << 4));
        const char* wl = (const char*)(wrow_lo + (c << 6) + (bq << 4));
        const uint32_t db = db0 + bo;
        cp16(db,      wh,      16);
        cp16(db + 16, wh + 16, 16);
        cp16(db + B_T_B,      wl,      16);
        cp16(db + B_T_B + 16, wl + 16, 16);
    };

    // ---- compute geometry
    const int wm  = wid & 1;
    const int wn  = wid >> 1;
    const int m0w = wm * 64;
    const int n0w = wn * 16;
    const int g   = lane >> 2;
    const int tk  = (lane & 3) * 2;

    uint32_t abase[4], bbase[2];
#pragma unroll
    for (int mf = 0; mf < 4; mf++)
        abase[mf] = smb + (m0w + mf * 16 + (lane & 15)) * SROW_B + ((lane & 16) ? 16 : 0);
#pragma unroll
    for (int nf = 0; nf < 2; nf++)
        bbase[nf] = smb + BHI_OFF + (n0w + nf * 8 + (lane & 7)) * SROW_B + ((lane & 8) ? 16 : 0);

    float    accf[4][2][4];
    uint32_t acch[4][2][2];
#pragma unroll
    for (int mf = 0; mf < 4; mf++)
#pragma unroll
        for (int nf = 0; nf < 2; nf++) {
#pragma unroll
            for (int r = 0; r < 4; r++) accf[mf][nf][r] = 0.f;
            acch[mf][nf][0] = 0u; acch[mf][nf][1] = 0u;
        }

    // ---- pipeline
    stage(cbeg, 0);
    CP_COMMIT();

    for (int c = cbeg; c < cend; ++c) {
        const int buf = (c - cbeg) & 1;
        if (c + 1 < cend) {
            stage(c + 1, buf ^ 1);
            CP_COMMIT();
            CP_WAIT1();
        } else {
            CP_WAIT0();
        }
        __syncthreads();

        const uint32_t bo = (uint32_t)buf * BUF_B;
#pragma unroll
        for (int ks = 0; ks < 4; ++ks) {
            uint32_t ah[4][4], al[4][4], bh[2][2], bl[2][2];
#pragma unroll
            for (int mf = 0; mf < 4; mf++) {
                ldsm4(ah[mf], abase[mf] + bo + ks * 32);
                ldsm4(al[mf], abase[mf] + bo + ALO_OFF + ks * 32);
            }
#pragma unroll
            for (int nf = 0; nf < 2; nf++) {
                ldsm2(bh[nf], bbase[nf] + bo + ks * 32);
                ldsm2(bl[nf], bbase[nf] + bo + B_T_B + ks * 32);
            }
#pragma unroll
            for (int mf = 0; mf < 4; mf++)
#pragma unroll
                for (int nf = 0; nf < 2; nf++) {
                    mma_f32(accf[mf][nf], ah[mf], bh[nf]);
                    mma_f16(acch[mf][nf], ah[mf], bl[nf]);
                    mma_f16(acch[mf][nf], al[mf], bh[nf]);
                }
        }
        __syncthreads();
    }

    // ---- epilogue: total = accf + acch/2048
#pragma unroll
    for (int mf = 0; mf < 4; mf++) {
        const __half2 h01 = *reinterpret_cast<const __half2*>(&acch[mf][0][0]);
        const __half2 h23 = *reinterpret_cast<const __half2*>(&acch[mf][0][1]);
        const __half2 i01 = *reinterpret_cast<const __half2*>(&acch[mf][1][0]);
        const __half2 i23 = *reinterpret_cast<const __half2*>(&acch[mf][1][1]);
        float cr[2][4];
        cr[0][0] = __half2float(h01.x); cr[0][1] = __half2float(h01.y);
        cr[0][2] = __half2float(h23.x); cr[0][3] = __half2float(h23.y);
        cr[1][0] = __half2float(i01.x); cr[1][1] = __half2float(i01.y);
        cr[1][2] = __half2float(i23.x); cr[1][3] = __half2float(i23.y);
#pragma unroll
        for (int half = 0; half < 2; half++) {
            const int p = m0 + m0w + mf * 16 + g + half * 8;
            if (p >= Mtot) continue;
            const int im = p / HW;
            const int pp = p - im * HW;
            float* orow = dst + (size_t)im * dstride + (size_t)pp * COUT + co0;
#pragma unroll
            for (int nf = 0; nf < 2; nf++) {
                const int col = n0w + nf * 8 + tk;
                float v0 = accf[mf][nf][half * 2 + 0] + LO_INV * cr[nf][half * 2 + 0];
                float v1 = accf[mf][nf][half * 2 + 1] + LO_INV * cr[nf][half * 2 + 1];
                float2* d2 = (float2*)(orow + col);
                if (accum) {
                    float2 o = *d2;
                    v0 += o.x; v1 += o.y;
                } else if (bs) {
                    v0 += bs[co0 + col];
                    v1 += bs[co0 + col + 1];
                }
                d2->x = v0; d2->y = v1;
            }
        }
    }
}

// ---------------------------------------------------------------------------
// Fused prep: z<4 -> weight transpose + split; z==4 -> x split.
// grid (200, 32, 5), block (32, 8)
// ---------------------------------------------------------------------------
__global__ void prep(const float* __restrict__ w0, const float* __restrict__ w1,
                     const float* __restrict__ w2, const float* __restrict__ w3,
                     __half* __restrict__ whi, __half* __restrict__ wlo,
                     const float* __restrict__ x,
                     __half* __restrict__ ah, __half* __restrict__ al)
{
    const int z = blockIdx.z;
    if (z < 4) {
        const float* w = (z == 0) ? w0 : (z == 1) ? w1 : (z == 2) ? w2 : w3;
        __half* whiz = whi + (size_t)z * W_ELEMS;
        __half* wloz = wlo + (size_t)z * W_ELEMS;
        __shared__ float tile[32][33];
        const int k0  = blockIdx.x * 32;
        const int co0 = blockIdx.y * 32;
        const int tx = threadIdx.x, ty = threadIdx.y;
#pragma unroll
        for (int i = 0; i < 4; i++)
            tile[ty + i * 8][tx] = w[(size_t)(k0 + ty + i * 8) * COUT + co0 + tx];
        __syncthreads();
#pragma unroll
        for (int i = 0; i < 4; i++) {
            const int co = co0 + ty + i * 8;
            const int k  = k0 + tx;
            const float v = tile[tx][ty + i * 8];
            const __half h = __float2half_rn(v);
            whiz[(size_t)co * KTOT + k] = h;
            wloz[(size_t)co * KTOT + k] = __float2half_rn((v - __half2float(h)) * LO_SCALE);
        }
    } else {
        const int tid = threadIdx.y * 32 + threadIdx.x;
        const size_t base = ((size_t)blockIdx.y * 200 + blockIdx.x) * 256 + tid;
        const size_t stride = (size_t)200 * 32 * 256;
        for (size_t i = base; i < SEQ_ELEMS; i += stride) {
            const float v = x[i];
            const __half h = __float2half_rn(v);
            ah[i] = h;
            al[i] = __float2half_rn((v - __half2float(h)) * LO_SCALE);
        }
    }
}

// ---------------------------------------------------------------------------
// LSTM pointwise (+ emit hidden-state hi/lo); sums split-K partials
// ---------------------------------------------------------------------------
__device__ __forceinline__ float hsig(float x)
{
    return fminf(fmaxf(0.2f * x + 0.5f, 0.f), 1.f);
}

__global__ void lstm_point(const float* __restrict__ xg_t,
                           const float* __restrict__ xg2,
                           float* __restrict__ cbuf,
                           float* __restrict__ h_out,
                           __half* __restrict__ hh,
                           __half* __restrict__ hl,
                           int first)
{
    int idx = blockIdx.x * 256 + threadIdx.x;
    if (idx >= (int)STATE_ELEMS) return;
    int b   = idx / (HW * Ff);
    int rem = idx - b * (HW * Ff);
    int pix = rem >> 8;
    int ch  = rem & 255;
    const float* gp = xg_t + (size_t)b * (Tt * HW * COUT) + (size_t)pix * COUT + ch;
    float gi = gp[0], gf = gp[256], gc = gp[512], go = gp[768];
    if (xg2) {
        const float* g2 = xg2 + ((size_t)b * HW + pix) * COUT + ch;
        gi += g2[0]; gf += g2[256]; gc += g2[512]; go += g2[768];
    }
    float i_ = hsig(gi);
    float f_ = hsig(gf);
    float cc = fmaxf(gc, 0.f);
    float o_ = hsig(go);
    float cp = first ? 0.f : cbuf[idx];
    float cn = f_ * cp + i_ * cc;
    cbuf[idx] = cn;
    float h = o_ * fmaxf(cn, 0.f);
    size_t oidx = (size_t)b * (Tt * HW * Ff) + rem;
    h_out[oidx] = h;
    __half hb = __float2half_rn(h);
    hh[oidx] = hb;
    hl[oidx] = __float2half_rn((h - __half2float(hb)) * LO_SCALE);
}

// ---------------------------------------------------------------------------
// Instance norm
// ---------------------------------------------------------------------------
__global__ void inorm_stats(const float* __restrict__ seq, float2* __restrict__ stats)
{
    int b  = blockIdx.x >> 8;
    int ch = blockIdx.x & 255;
    const float* base = seq + (size_t)b * Tt * HW * Ff + ch;
    float s = 0.f, s2 = 0.f;
    for (int e = threadIdx.x; e < Tt * HW; e += 256) {
        float v = base[(size_t)e * Ff];
        s += v; s2 += v * v;
    }
    __shared__ float rs[256], rq[256];
    rs[threadIdx.x] = s;  rq[threadIdx.x] = s2;
    __syncthreads();
    for (int st = 128; st > 0; st >>= 1) {
        if (threadIdx.x < st) {
            rs[threadIdx.x] += rs[threadIdx.x + st];
            rq[threadIdx.x] += rq[threadIdx.x + st];
        }
        __syncthreads();
    }
    if (threadIdx.x == 0) {
        const float inv = 1.f / (float)(Tt * HW);
        float mu  = rs[0] * inv;
        float var = rq[0] * inv - mu * mu;
        stats[blockIdx.x] = make_float2(mu, rsqrtf(var + 1e-3f));
    }
}

__global__ void inorm_apply(const float* __restrict__ in,
                            const float2* __restrict__ stats,
                            const float* __restrict__ gamma,
                            const float* __restrict__ beta,
                            float* __restrict__ out,
                            __half* __restrict__ sh,
                            __half* __restrict__ sl)
{
    size_t idx = (size_t)blockIdx.x * 256 + threadIdx.x;
    if (idx >= SEQ_ELEMS) return;
    int ch = (int)(idx & 255);
    int b  = (int)(idx / ((size_t)Tt * HW * Ff));
    float2 st = stats[b * 256 + ch];
    float v = gamma[ch] * (in[idx] - st.x) * st.y + beta[ch];
    out[idx] = v;
    if (sh) {
        __half h = __float2half_rn(v);
        sh[idx] = h;
        sl[idx] = __float2half_rn((v - __half2float(h)) * LO_SCALE);
    }
}

__global__ void copy_states(const float* __restrict__ seq2,
                            const float* __restrict__ cbuf,
                            float* __restrict__ h2, float* __restrict__ c2)
{
    int idx = blockIdx.x * 256 + threadIdx.x;
    if (idx >= (int)STATE_ELEMS) return;
    int b   = idx / (HW * Ff);
    int rem = idx - b * (HW * Ff);
    h2[idx] = seq2[(size_t)b * Tt * HW * Ff + (size_t)(Tt - 1) * HW * Ff + rem];
    c2[idx] = cbuf[idx];
}

// ---------------------------------------------------------------------------
// Orchestration
// ---------------------------------------------------------------------------
extern "C" void kernel_launch(void* const* d_in, const int* /*in_sizes*/, int /*n_in*/,
                              void* d_out, int /*out_size*/)
{
    const float* x   = (const float*)d_in[0];
    const float* k1  = (const float*)d_in[1];
    const float* rk1 = (const float*)d_in[2];
    const float* b1  = (const float*)d_in[3];
    const float* g1  = (const float*)d_in[4];
    const float* bt1 = (const float*)d_in[5];
    const float* k2  = (const float*)d_in[6];
    const float* rk2 = (const float*)d_in[7];
    const float* b2  = (const float*)d_in[8];
    const float* g2  = (const float*)d_in[9];
    const float* bt2 = (const float*)d_in[10];

    float* out    = (float*)d_out;
    float* out_h2 = out + SEQ_ELEMS;
    float* out_c2 = out_h2 + STATE_ELEMS;

    float *xg, *xg2, *seq1, *seq2, *cbuf;
    float2* stats;
    __half *ah, *al, *hh, *hl, *whi, *wlo;
    cudaGetSymbolAddress((void**)&xg,    g_xg);
    cudaGetSymbolAddress((void**)&xg2,   g_xg2);
    cudaGetSymbolAddress((void**)&seq1,  g_seq1);
    cudaGetSymbolAddress((void**)&seq2,  g_seq2);
    cudaGetSymbolAddress((void**)&cbuf,  g_c);
    cudaGetSymbolAddress((void**)&stats, g_stats);
    cudaGetSymbolAddress((void**)&ah,    g_ah);
    cudaGetSymbolAddress((void**)&al,    g_al);
    cudaGetSymbolAddress((void**)&hh,    g_hh);
    cudaGetSymbolAddress((void**)&hl,    g_hl);
    cudaGetSymbolAddress((void**)&whi,   g_whi);
    cudaGetSymbolAddress((void**)&wlo,   g_wlo);

    cudaFuncSetAttribute(conv_mma, cudaFuncAttributeMaxDynamicSharedMemorySize, SMEM_TOT);

    // single fused prep launch (weights z=0..3, x split z=4)
    prep<<<dim3(KTOT / 32, COUT / 32, 5), dim3(32, 8)>>>(
        k1, rk1, k2, rk2, whi, wlo, x, ah, al);

    const int Min  = Bb * Tt * HW;                      // 21504
    const int Mrec = Bb * HW;                           // 1344
    const dim3 igrid(Min / MT, COUT / NT, 1);           // (168, 16, 1)
    const dim3 rgrid((Mrec + MT - 1) / MT, COUT / NT, 2); // (11, 16, 2)
    const int pblocks = (int)((STATE_ELEMS + 255) / 256);
    const int sblocks = (int)((SEQ_ELEMS + 255) / 256);
    const size_t XSTR  = (size_t)Tt * HW * COUT;
    const size_t X2STR = (size_t)HW * COUT;
    const size_t HSTR  = (size_t)Tt * HW * Ff;

    // ---------------- Layer 1 ----------------
    conv_mma<<<igrid, 256, SMEM_TOT>>>(
        ah, al, (size_t)HW * CIN, whi + 0 * W_ELEMS, wlo + 0 * W_ELEMS,
        b1, xg, (size_t)HW * COUT, nullptr, 0, Min);

    for (int t = 0; t < Tt; ++t) {
        if (t > 0)
            conv_mma<<<rgrid, 256, SMEM_TOT>>>(
                hh + (size_t)(t - 1) * HW * Ff, hl + (size_t)(t - 1) * HW * Ff, HSTR,
                whi + 1 * W_ELEMS, wlo + 1 * W_ELEMS, nullptr,
                xg + (size_t)t * HW * COUT, XSTR, xg2, X2STR, Mrec);
        lstm_point<<<pblocks, 256>>>(xg + (size_t)t * HW * COUT,
                                     (t > 0) ? xg2 : nullptr, cbuf,
                                     seq1 + (size_t)t * HW * Ff,
                                     hh + (size_t)t * HW * Ff,
                                     hl + (size_t)t * HW * Ff, t == 0);
    }
    inorm_stats<<<Bb * Ff, 256>>>(seq1, stats);
    inorm_apply<<<sblocks, 256>>>(seq1, stats, g1, bt1, seq1, ah, al);

    // ---------------- Layer 2 ----------------
    conv_mma<<<igrid, 256, SMEM_TOT>>>(
        ah, al, (size_t)HW * CIN, whi + 2 * W_ELEMS, wlo + 2 * W_ELEMS,
        b2, xg, (size_t)HW * COUT, nullptr, 0, Min);

    for (int t = 0; t < Tt; ++t) {
        if (t > 0)
            conv_mma<<<rgrid, 256, SMEM_TOT>>>(
                hh + (size_t)(t - 1) * HW * Ff, hl + (size_t)(t - 1) * HW * Ff, HSTR,
                whi + 3 * W_ELEMS, wlo + 3 * W_ELEMS, nullptr,
                xg + (size_t)t * HW * COUT, XSTR, xg2, X2STR, Mrec);
        lstm_point<<<pblocks, 256>>>(xg + (size_t)t * HW * COUT,
                                     (t > 0) ? xg2 : nullptr, cbuf,
                                     seq2 + (size_t)t * HW * Ff,
                                     hh + (size_t)t * HW * Ff,
                                     hl + (size_t)t * HW * Ff, t == 0);
    }

    copy_states<<<pblocks, 256>>>(seq2, cbuf, out_h2, out_c2);
    inorm_stats<<<Bb * Ff, 256>>>(seq2, stats);
    inorm_apply<<<sblocks, 256>>>(seq2, stats, g2, bt2, out, nullptr, nullptr);
}

// round 8
// speedup vs baseline: 1.0810x; 1.0810x over previous
#include <cuda_runtime.h>
#include <cuda_fp16.h>
#include <cstdint>
#include <math.h>

// ---------------------------------------------------------------------------
// Problem constants
// ---------------------------------------------------------------------------
namespace {
constexpr int Hh   = 16;
constexpr int Ww   = 21;
constexpr int HW   = Hh * Ww;        // 336
constexpr int CIN  = 256;
constexpr int COUT = 1024;           // 4*F
constexpr int Tt   = 16;
constexpr int Bb   = 4;
constexpr int Ff   = 256;
constexpr int KTOT = 25 * CIN;       // 6400

constexpr size_t SEQ_ELEMS   = (size_t)Bb * Tt * HW * Ff;      // 5,505,024
constexpr size_t STATE_ELEMS = (size_t)Bb * HW * Ff;           // 344,064
constexpr size_t XG_ELEMS    = (size_t)Bb * Tt * HW * COUT;    // 22,020,096
constexpr size_t XG2_ELEMS   = (size_t)Bb * HW * COUT;         // 1,376,256
constexpr size_t W_ELEMS     = (size_t)KTOT * COUT;            // 6,553,600

constexpr float LO_SCALE = 2048.0f;          // exact power of two
constexpr float LO_INV   = 1.0f / 2048.0f;

constexpr int NCHUNK = KTOT / 64;            // 100 chunks of k=64
constexpr int NT     = 64;                   // CTA cout tile (fixed)
constexpr int SROW_B = 144;                  // padded row stride (bytes)
constexpr int B_T_B  = NT * SROW_B;          // 9216
}

// ---------------------------------------------------------------------------
// Scratch (device globals — no allocation allowed)
// ---------------------------------------------------------------------------
__device__ float  g_xg[XG_ELEMS];
__device__ float  g_xg2[XG2_ELEMS];
__device__ float  g_seq1[SEQ_ELEMS];
__device__ float  g_seq2[SEQ_ELEMS];
__device__ float  g_c[STATE_ELEMS];
__device__ float2 g_stats[Bb * Ff];

__device__ __align__(16) __half g_ah[SEQ_ELEMS];      // conv input hi
__device__ __align__(16) __half g_al[SEQ_ELEMS];      // conv input lo * 2048
__device__ __align__(16) __half g_hh[SEQ_ELEMS];      // hidden hi
__device__ __align__(16) __half g_hl[SEQ_ELEMS];      // hidden lo * 2048
__device__ __align__(16) __half g_whi[4][W_ELEMS];    // weights [co][k] hi
__device__ __align__(16) __half g_wlo[4][W_ELEMS];    // weights [co][k] lo * 2048

// ---------------------------------------------------------------------------
// PTX helpers (portable to plain sm_103)
// ---------------------------------------------------------------------------
__device__ __forceinline__ uint32_t smem_u32(const void* p) {
    uint32_t a;
    asm("{ .reg .u64 t; cvta.to.shared.u64 t, %1; cvt.u32.u64 %0, t; }" : "=r"(a) : "l"(p));
    return a;
}
__device__ __forceinline__ void cp16(uint32_t dst, const void* src, uint32_t srcsz) {
    asm volatile("cp.async.cg.shared.global [%0], [%1], 16, %2;"
                 :: "r"(dst), "l"(src), "r"(srcsz) : "memory");
}
#define CP_COMMIT() asm volatile("cp.async.commit_group;" ::: "memory")
#define CP_WAIT1()  asm volatile("cp.async.wait_group 1;" ::: "memory")
#define CP_WAIT0()  asm volatile("cp.async.wait_group 0;" ::: "memory")

__device__ __forceinline__ void ldsm4(uint32_t* r, uint32_t addr) {
    asm volatile("ldmatrix.sync.aligned.m8n8.x4.shared.b16 {%0,%1,%2,%3}, [%4];"
                 : "=r"(r[0]), "=r"(r[1]), "=r"(r[2]), "=r"(r[3]) : "r"(addr));
}
// hi*hi term: fp32 accumulate
__device__ __forceinline__ void mma_f32(float* d, const uint32_t* a, const uint32_t* b)
{
    asm volatile(
        "mma.sync.aligned.m16n8k16.row.col.f32.f16.f16.f32 "
        "{%0,%1,%2,%3}, {%4,%5,%6,%7}, {%8,%9}, {%0,%1,%2,%3};"
        : "+f"(d[0]), "+f"(d[1]), "+f"(d[2]), "+f"(d[3])
        : "r"(a[0]), "r"(a[1]), "r"(a[2]), "r"(a[3]), "r"(b[0]), "r"(b[1]));
}
// cross terms: fp16 accumulate (operands pre-scaled by 2048 keep products normal)
__device__ __forceinline__ void mma_f16(uint32_t* d, const uint32_t* a, const uint32_t* b)
{
    asm volatile(
        "mma.sync.aligned.m16n8k16.row.col.f16.f16.f16.f16 "
        "{%0,%1}, {%2,%3,%4,%5}, {%6,%7}, {%0,%1};"
        : "+r"(d[0]), "+r"(d[1])
        : "r"(a[0]), "r"(a[1]), "r"(a[2]), "r"(a[3]), "r"(b[0]), "r"(b[1]));
}

// ---------------------------------------------------------------------------
// Implicit-GEMM 5x5 SAME conv, 256 -> 1024, fp16 3-term split:
//   out = Ahi*Bhi (f32 acc) + (Ahi*Blo' + Alo'*Bhi) (f16 acc) / 2048
// Template: CM = CTA pixel tile (128 input / 64 recurrent), WM = warps in M.
// 8 warps arranged WM x (8/WM); warp tile = 32 x (WM*8). MF = 2 always.
// grid = (ceil(Mtot/CM), 16, Z). Z==1: full K + bias. Z==2: split-K halves.
// ---------------------------------------------------------------------------
template <int CM, int WM, int MINB>
__global__ __launch_bounds__(256, MINB) void conv_mma(
    const __half* __restrict__ a_hi, const __half* __restrict__ a_lo,
    size_t a_img_stride,
    const __half* __restrict__ w_hi, const __half* __restrict__ w_lo,
    const float* __restrict__ bias,
    float* __restrict__ out, size_t out_img_stride,
    float* __restrict__ out2, size_t out2_img_stride,
    int Mtot)
{
    constexpr int NF    = WM;            // n-fragments per warp (8-col units)
    constexpr int NPAIR = NF / 2;        // ldmatrix.x4 pairs for B
    constexpr int A_T_B = CM * SROW_B;
    constexpr int ALO   = A_T_B;
    constexpr int BHI   = 2 * A_T_B;
    constexpr int BUF   = 2 * A_T_B + 2 * B_T_B;
    constexpr int TPR   = 256 / CM;      // staging threads per A row
    constexpr int CPQ   = 8 / TPR;       // cp16 per thread per A operand

    extern __shared__ __align__(16) char sm[];
    const uint32_t smb = smem_u32(sm);

    const int tid  = threadIdx.x;
    const int lane = tid & 31;
    const int wid  = tid >> 5;
    const int m0   = blockIdx.x * CM;
    const int co0  = blockIdx.y * NT;

    int cbeg = 0, cend = NCHUNK;
    float* dst = out;
    size_t dstride = out_img_stride;
    bool accum = false;
    const float* bs = bias;
    if (gridDim.z == 2) {
        bs = nullptr;
        if (blockIdx.z == 0) { cend = NCHUNK / 2; accum = true; }
        else { cbeg = NCHUNK / 2; dst = out2; dstride = out2_img_stride; }
    }

    // ---- staging geometry
    const int arow = tid / TPR;
    const int asub = tid % TPR;
    int pc = m0 + arow; if (pc >= Mtot) pc = Mtot - 1;
    const int img = pc / HW;
    const int rm  = pc - img * HW;
    const int py  = rm / Ww;
    const int px  = rm - py * Ww;
    const __half* aimg_hi = a_hi + (size_t)img * a_img_stride;
    const __half* aimg_lo = a_lo + (size_t)img * a_img_stride;

    const int brow = tid >> 2;
    const int bq   = tid & 3;
    const __half* wrow_hi = w_hi + (size_t)(co0 + brow) * KTOT;
    const __half* wrow_lo = w_lo + (size_t)(co0 + brow) * KTOT;

    const uint32_t da0 = smb + arow * SROW_B + asub * (128 / TPR);
    const uint32_t db0 = smb + BHI + brow * SROW_B + (bq << 5);

    auto stage = [&](int c, int buf) {
        const uint32_t bo = (uint32_t)buf * BUF;
        const int tp  = c >> 2;
        const int ci0 = (c & 3) << 6;
        const int dy  = tp / 5;
        const int dx  = tp - dy * 5;
        const int gy  = py + dy - 2;
        const int gx  = px + dx - 2;
        const bool inb = (gy >= 0 && gy < Hh && gx >= 0 && gx < Ww);
        const uint32_t sz = inb ? 16u : 0u;
        const size_t off = inb ?
            ((((size_t)(gy * Ww + gx)) << 8) + ci0 + asub * (64 / TPR)) : 0;
        const char* sh = (const char*)(aimg_hi + off);
        const char* sl = (const char*)(aimg_lo + off);
        const uint32_t da = da0 + bo;
#pragma unroll
        for (int q = 0; q < CPQ; q++) {
            cp16(da + q * 16,       sh + q * 16, sz);
            cp16(da + ALO + q * 16, sl + q * 16, sz);
        }
        const char* wh = (const char*)(wrow_hi + (c << 6) + (bq << 4));
        const char* wl = (const char*)(wrow_lo + (c << 6) + (bq << 4));
        const uint32_t db = db0 + bo;
        cp16(db,      wh,      16);
        cp16(db + 16, wh + 16, 16);
        cp16(db + B_T_B,      wl,      16);
        cp16(db + B_T_B + 16, wl + 16, 16);
    };

    // ---- compute geometry: 8 warps = WM (m) x 8/WM (n); warp tile 32 x NF*8
    const int wm  = wid & (WM - 1);
    const int wn  = wid / WM;
    const int m0w = wm * 32;
    const int n0w = wn * (NF * 8);
    const int g   = lane >> 2;
    const int tk  = (lane & 3) * 2;

    uint32_t abase[2], bbase[NPAIR];
#pragma unroll
    for (int mf = 0; mf < 2; mf++)
        abase[mf] = smb + (m0w + mf * 16 + (lane & 15)) * SROW_B + ((lane & 16) ? 16 : 0);
#pragma unroll
    for (int p = 0; p < NPAIR; p++)
        bbase[p] = smb + BHI + (n0w + p * 16 + (lane & 15)) * SROW_B + ((lane & 16) ? 16 : 0);

    float    accf[2][NF][4];
    uint32_t acch[2][NF][2];
#pragma unroll
    for (int mf = 0; mf < 2; mf++)
#pragma unroll
        for (int nf = 0; nf < NF; nf++) {
#pragma unroll
            for (int r = 0; r < 4; r++) accf[mf][nf][r] = 0.f;
            acch[mf][nf][0] = 0u; acch[mf][nf][1] = 0u;
        }

    // ---- pipeline
    stage(cbeg, 0);
    CP_COMMIT();

    for (int c = cbeg; c < cend; ++c) {
        const int buf = (c - cbeg) & 1;
        if (c + 1 < cend) {
            stage(c + 1, buf ^ 1);
            CP_COMMIT();
            CP_WAIT1();
        } else {
            CP_WAIT0();
        }
        __syncthreads();

        const uint32_t bo = (uint32_t)buf * BUF;
#pragma unroll
        for (int ks = 0; ks < 4; ++ks) {
            uint32_t ah[2][4], al[2][4], bh4[NPAIR][4], bl4[NPAIR][4];
#pragma unroll
            for (int mf = 0; mf < 2; mf++) {
                ldsm4(ah[mf], abase[mf] + bo + ks * 32);
                ldsm4(al[mf], abase[mf] + bo + ALO + ks * 32);
            }
#pragma unroll
            for (int p = 0; p < NPAIR; p++) {
                ldsm4(bh4[p], bbase[p] + bo + ks * 32);
                ldsm4(bl4[p], bbase[p] + bo + B_T_B + ks * 32);
            }
            // x4 B layout: r0 = rows 0-7 k0-7, r1 = rows 8-15 k0-7,
            //              r2 = rows 0-7 k8-15, r3 = rows 8-15 k8-15
#pragma unroll
            for (int mf = 0; mf < 2; mf++)
#pragma unroll
                for (int p = 0; p < NPAIR; p++)
#pragma unroll
                    for (int e = 0; e < 2; e++) {
                        uint32_t bh[2] = { bh4[p][e], bh4[p][e + 2] };
                        uint32_t bl[2] = { bl4[p][e], bl4[p][e + 2] };
                        const int nf = p * 2 + e;
                        mma_f32(accf[mf][nf], ah[mf], bh);
                        mma_f16(acch[mf][nf], ah[mf], bl);
                        mma_f16(acch[mf][nf], al[mf], bh);
                    }
        }
        __syncthreads();
    }

    // ---- epilogue: total = accf + acch/2048
#pragma unroll
    for (int mf = 0; mf < 2; mf++) {
        float cr[NF][4];
#pragma unroll
        for (int nf = 0; nf < NF; nf++) {
            const __half2 c01 = *reinterpret_cast<const __half2*>(&acch[mf][nf][0]);
            const __half2 c23 = *reinterpret_cast<const __half2*>(&acch[mf][nf][1]);
            cr[nf][0] = __half2float(c01.x); cr[nf][1] = __half2float(c01.y);
            cr[nf][2] = __half2float(c23.x); cr[nf][3] = __half2float(c23.y);
        }
#pragma unroll
        for (int half = 0; half < 2; half++) {
            const int p = m0 + m0w + mf * 16 + g + half * 8;
            if (p >= Mtot) continue;
            const int im = p / HW;
            const int pp = p - im * HW;
            float* orow = dst + (size_t)im * dstride + (size_t)pp * COUT + co0;
#pragma unroll
            for (int nf = 0; nf < NF; nf++) {
                const int col = n0w + nf * 8 + tk;
                float v0 = accf[mf][nf][half * 2 + 0] + LO_INV * cr[nf][half * 2 + 0];
                float v1 = accf[mf][nf][half * 2 + 1] + LO_INV * cr[nf][half * 2 + 1];
                float2* d2 = (float2*)(orow + col);
                if (accum) {
                    float2 o = *d2;
                    v0 += o.x; v1 += o.y;
                } else if (bs) {
                    v0 += bs[co0 + col];
                    v1 += bs[co0 + col + 1];
                }
                d2->x = v0; d2->y = v1;
            }
        }
    }
}

// ---------------------------------------------------------------------------
// Fused prep: z<4 -> weight transpose + split; z==4 -> x split.
// ---------------------------------------------------------------------------
__global__ void prep(const float* __restrict__ w0, const float* __restrict__ w1,
                     const float* __restrict__ w2, const float* __restrict__ w3,
                     __half* __restrict__ whi, __half* __restrict__ wlo,
                     const float* __restrict__ x,
                     __half* __restrict__ ah, __half* __restrict__ al)
{
    const int z = blockIdx.z;
    if (z < 4) {
        const float* w = (z == 0) ? w0 : (z == 1) ? w1 : (z == 2) ? w2 : w3;
        __half* whiz = whi + (size_t)z * W_ELEMS;
        __half* wloz = wlo + (size_t)z * W_ELEMS;
        __shared__ float tile[32][33];
        const int k0  = blockIdx.x * 32;
        const int co0 = blockIdx.y * 32;
        const int tx = threadIdx.x, ty = threadIdx.y;
#pragma unroll
        for (int i = 0; i < 4; i++)
            tile[ty + i * 8][tx] = w[(size_t)(k0 + ty + i * 8) * COUT + co0 + tx];
        __syncthreads();
#pragma unroll
        for (int i = 0; i < 4; i++) {
            const int co = co0 + ty + i * 8;
            const int k  = k0 + tx;
            const float v = tile[tx][ty + i * 8];
            const __half h = __float2half_rn(v);
            whiz[(size_t)co * KTOT + k] = h;
            wloz[(size_t)co * KTOT + k] = __float2half_rn((v - __half2float(h)) * LO_SCALE);
        }
    } else {
        const int tid = threadIdx.y * 32 + threadIdx.x;
        const size_t base = ((size_t)blockIdx.y * 200 + blockIdx.x) * 256 + tid;
        const size_t stride = (size_t)200 * 32 * 256;
        for (size_t i = base; i < SEQ_ELEMS; i += stride) {
            const float v = x[i];
            const __half h = __float2half_rn(v);
            ah[i] = h;
            al[i] = __float2half_rn((v - __half2float(h)) * LO_SCALE);
        }
    }
}

// ---------------------------------------------------------------------------
// LSTM pointwise (+ emit hidden-state hi/lo); sums split-K partials
// ---------------------------------------------------------------------------
__device__ __forceinline__ float hsig(float x)
{
    return fminf(fmaxf(0.2f * x + 0.5f, 0.f), 1.f);
}

__global__ void lstm_point(const float* __restrict__ xg_t,
                           const float* __restrict__ xg2,
                           float* __restrict__ cbuf,
                           float* __restrict__ h_out,
                           __half* __restrict__ hh,
                           __half* __restrict__ hl,
                           int first)
{
    int idx = blockIdx.x * 256 + threadIdx.x;
    if (idx >= (int)STATE_ELEMS) return;
    int b   = idx / (HW * Ff);
    int rem = idx - b * (HW * Ff);
    int pix = rem >> 8;
    int ch  = rem & 255;
    const float* gp = xg_t + (size_t)b * (Tt * HW * COUT) + (size_t)pix * COUT + ch;
    float gi = gp[0], gf = gp[256], gc = gp[512], go = gp[768];
    if (xg2) {
        const float* g2 = xg2 + ((size_t)b * HW + pix) * COUT + ch;
        gi += g2[0]; gf += g2[256]; gc += g2[512]; go += g2[768];
    }
    float i_ = hsig(gi);
    float f_ = hsig(gf);
    float cc = fmaxf(gc, 0.f);
    float o_ = hsig(go);
    float cp = first ? 0.f : cbuf[idx];
    float cn = f_ * cp + i_ * cc;
    cbuf[idx] = cn;
    float h = o_ * fmaxf(cn, 0.f);
    size_t oidx = (size_t)b * (Tt * HW * Ff) + rem;
    h_out[oidx] = h;
    __half hb = __float2half_rn(h);
    hh[oidx] = hb;
    hl[oidx] = __float2half_rn((h - __half2float(hb)) * LO_SCALE);
}

// ---------------------------------------------------------------------------
// Instance norm
// ---------------------------------------------------------------------------
__global__ void inorm_stats(const float* __restrict__ seq, float2* __restrict__ stats)
{
    int b  = blockIdx.x >> 8;
    int ch = blockIdx.x & 255;
    const float* base = seq + (size_t)b * Tt * HW * Ff + ch;
    float s = 0.f, s2 = 0.f;
    for (int e = threadIdx.x; e < Tt * HW; e += 256) {
        float v = base[(size_t)e * Ff];
        s += v; s2 += v * v;
    }
    __shared__ float rs[256], rq[256];
    rs[threadIdx.x] = s;  rq[threadIdx.x] = s2;
    __syncthreads();
    for (int st = 128; st > 0; st >>= 1) {
        if (threadIdx.x < st) {
            rs[threadIdx.x] += rs[threadIdx.x + st];
            rq[threadIdx.x] += rq[threadIdx.x + st];
        }
        __syncthreads();
    }
    if (threadIdx.x == 0) {
        const float inv = 1.f / (float)(Tt * HW);
        float mu  = rs[0] * inv;
        float var = rq[0] * inv - mu * mu;
        stats[blockIdx.x] = make_float2(mu, rsqrtf(var + 1e-3f));
    }
}

__global__ void inorm_apply(const float* __restrict__ in,
                            const float2* __restrict__ stats,
                            const float* __restrict__ gamma,
                            const float* __restrict__ beta,
                            float* __restrict__ out,
                            __half* __restrict__ sh,
                            __half* __restrict__ sl)
{
    size_t idx = (size_t)blockIdx.x * 256 + threadIdx.x;
    if (idx >= SEQ_ELEMS) return;
    int ch = (int)(idx & 255);
    int b  = (int)(idx / ((size_t)Tt * HW * Ff));
    float2 st = stats[b * 256 + ch];
    float v = gamma[ch] * (in[idx] - st.x) * st.y + beta[ch];
    out[idx] = v;
    if (sh) {
        __half h = __float2half_rn(v);
        sh[idx] = h;
        sl[idx] = __float2half_rn((v - __half2float(h)) * LO_SCALE);
    }
}

__global__ void copy_states(const float* __restrict__ seq2,
                            const float* __restrict__ cbuf,
                            float* __restrict__ h2, float* __restrict__ c2)
{
    int idx = blockIdx.x * 256 + threadIdx.x;
    if (idx >= (int)STATE_ELEMS) return;
    int b   = idx / (HW * Ff);
    int rem = idx - b * (HW * Ff);
    h2[idx] = seq2[(size_t)b * Tt * HW * Ff + (size_t)(Tt - 1) * HW * Ff + rem];
    c2[idx] = cbuf[idx];
}

// ---------------------------------------------------------------------------
// Orchestration
// ---------------------------------------------------------------------------
extern "C" void kernel_launch(void* const* d_in, const int* /*in_sizes*/, int /*n_in*/,
                              void* d_out, int /*out_size*/)
{
    const float* x   = (const float*)d_in[0];
    const float* k1  = (const float*)d_in[1];
    const float* rk1 = (const float*)d_in[2];
    const float* b1  = (const float*)d_in[3];
    const float* g1  = (const float*)d_in[4];
    const float* bt1 = (const float*)d_in[5];
    const float* k2  = (const float*)d_in[6];
    const float* rk2 = (const float*)d_in[7];
    const float* b2  = (const float*)d_in[8];
    const float* g2  = (const float*)d_in[9];
    const float* bt2 = (const float*)d_in[10];

    float* out    = (float*)d_out;
    float* out_h2 = out + SEQ_ELEMS;
    float* out_c2 = out_h2 + STATE_ELEMS;

    float *xg, *xg2, *seq1, *seq2, *cbuf;
    float2* stats;
    __half *ah, *al, *hh, *hl, *whi, *wlo;
    cudaGetSymbolAddress((void**)&xg,    g_xg);
    cudaGetSymbolAddress((void**)&xg2,   g_xg2);
    cudaGetSymbolAddress((void**)&seq1,  g_seq1);
    cudaGetSymbolAddress((void**)&seq2,  g_seq2);
    cudaGetSymbolAddress((void**)&cbuf,  g_c);
    cudaGetSymbolAddress((void**)&stats, g_stats);
    cudaGetSymbolAddress((void**)&ah,    g_ah);
    cudaGetSymbolAddress((void**)&al,    g_al);
    cudaGetSymbolAddress((void**)&hh,    g_hh);
    cudaGetSymbolAddress((void**)&hl,    g_hl);
    cudaGetSymbolAddress((void**)&whi,   g_whi);
    cudaGetSymbolAddress((void**)&wlo,   g_wlo);

    // input conv: CM=128, 4m x 2n warps, 2 CTAs/SM
    constexpr int SMEM_IN  = 2 * (2 * 128 * SROW_B + 2 * B_T_B);   // 110592
    // recurrent conv: CM=64, 2m x 4n warps, 3 CTAs/SM
    constexpr int SMEM_REC = 2 * (2 * 64 * SROW_B + 2 * B_T_B);    // 73728
    cudaFuncSetAttribute((const void*)conv_mma<128, 4, 2>,
                         cudaFuncAttributeMaxDynamicSharedMemorySize, SMEM_IN);
    cudaFuncSetAttribute((const void*)conv_mma<64, 2, 3>,
                         cudaFuncAttributeMaxDynamicSharedMemorySize, SMEM_REC);

    // single fused prep launch (weights z=0..3, x split z=4)
    prep<<<dim3(KTOT / 32, COUT / 32, 5), dim3(32, 8)>>>(
        k1, rk1, k2, rk2, whi, wlo, x, ah, al);

    const int Min  = Bb * Tt * HW;                      // 21504
    const int Mrec = Bb * HW;                           // 1344
    const dim3 igrid(Min / 128, COUT / NT, 1);          // (168, 16, 1)
    const dim3 rgrid(Mrec / 64, COUT / NT, 2);          // (21, 16, 2)
    const int pblocks = (int)((STATE_ELEMS + 255) / 256);
    const int sblocks = (int)((SEQ_ELEMS + 255) / 256);
    const size_t XSTR  = (size_t)Tt * HW * COUT;
    const size_t X2STR = (size_t)HW * COUT;
    const size_t HSTR  = (size_t)Tt * HW * Ff;

    // ---------------- Layer 1 ----------------
    conv_mma<128, 4, 2><<<igrid, 256, SMEM_IN>>>(
        ah, al, (size_t)HW * CIN, whi + 0 * W_ELEMS, wlo + 0 * W_ELEMS,
        b1, xg, (size_t)HW * COUT, nullptr, 0, Min);

    for (int t = 0; t < Tt; ++t) {
        if (t > 0)
            conv_mma<64, 2, 3><<<rgrid, 256, SMEM_REC>>>(
                hh + (size_t)(t - 1) * HW * Ff, hl + (size_t)(t - 1) * HW * Ff, HSTR,
                whi + 1 * W_ELEMS, wlo + 1 * W_ELEMS, nullptr,
                xg + (size_t)t * HW * COUT, XSTR, xg2, X2STR, Mrec);
        lstm_point<<<pblocks, 256>>>(xg + (size_t)t * HW * COUT,
                                     (t > 0) ? xg2 : nullptr, cbuf,
                                     seq1 + (size_t)t * HW * Ff,
                                     hh + (size_t)t * HW * Ff,
                                     hl + (size_t)t * HW * Ff, t == 0);
    }
    inorm_stats<<<Bb * Ff, 256>>>(seq1, stats);
    inorm_apply<<<sblocks, 256>>>(seq1, stats, g1, bt1, seq1, ah, al);

    // ---------------- Layer 2 ----------------
    conv_mma<128, 4, 2><<<igrid, 256, SMEM_IN>>>(
        ah, al, (size_t)HW * CIN, whi + 2 * W_ELEMS, wlo + 2 * W_ELEMS,
        b2, xg, (size_t)HW * COUT, nullptr, 0, Min);

    for (int t = 0; t < Tt; ++t) {
        if (t > 0)
            conv_mma<64, 2, 3><<<rgrid, 256, SMEM_REC>>>(
                hh + (size_t)(t - 1) * HW * Ff, hl + (size_t)(t - 1) * HW * Ff, HSTR,
                whi + 3 * W_ELEMS, wlo + 3 * W_ELEMS, nullptr,
                xg + (size_t)t * HW * COUT, XSTR, xg2, X2STR, Mrec);
        lstm_point<<<pblocks, 256>>>(xg + (size_t)t * HW * COUT,
                                     (t > 0) ? xg2 : nullptr, cbuf,
                                     seq2 + (size_t)t * HW * Ff,
                                     hh + (size_t)t * HW * Ff,
                                     hl + (size_t)t * HW * Ff, t == 0);
    }

    copy_states<<<pblocks, 256>>>(seq2, cbuf, out_h2, out_c2);
    inorm_stats<<<Bb * Ff, 256>>>(seq2, stats);
    inorm_apply<<<sblocks, 256>>>(seq2, stats, g2, bt2, out, nullptr, nullptr);
}

// round 9
// speedup vs baseline: 1.0852x; 1.0039x over previous
#include <cuda_runtime.h>
#include <cuda_fp16.h>
#include <cstdint>
#include <math.h>

// ---------------------------------------------------------------------------
// Problem constants
// ---------------------------------------------------------------------------
namespace {
constexpr int Hh   = 16;
constexpr int Ww   = 21;
constexpr int HW   = Hh * Ww;        // 336
constexpr int CIN  = 256;
constexpr int COUT = 1024;           // 4*F
constexpr int Tt   = 16;
constexpr int Bb   = 4;
constexpr int Ff   = 256;
constexpr int KTOT = 25 * CIN;       // 6400

constexpr size_t SEQ_ELEMS   = (size_t)Bb * Tt * HW * Ff;      // 5,505,024
constexpr size_t STATE_ELEMS = (size_t)Bb * HW * Ff;           // 344,064
constexpr size_t XG_ELEMS    = (size_t)Bb * Tt * HW * COUT;    // 22,020,096
constexpr size_t XG2_ELEMS   = (size_t)Bb * HW * COUT;         // 1,376,256
constexpr size_t W_ELEMS     = (size_t)KTOT * COUT;            // 6,553,600

constexpr float LO_SCALE = 2048.0f;          // exact power of two
constexpr float LO_INV   = 1.0f / 2048.0f;

constexpr int NCHUNK = KTOT / 64;            // 100 chunks of k=64
constexpr int NT     = 64;                   // CTA cout tile (fixed)
constexpr int SROW_B = 144;                  // padded row stride (bytes)
constexpr int B_T_B  = NT * SROW_B;          // 9216
}

// ---------------------------------------------------------------------------
// Scratch (device globals — no allocation allowed)
// ---------------------------------------------------------------------------
__device__ float  g_xg[XG_ELEMS];
__device__ float  g_xg2[XG2_ELEMS];
__device__ float  g_seq1[SEQ_ELEMS];
__device__ float  g_seq2[SEQ_ELEMS];
__device__ float  g_c[STATE_ELEMS];
__device__ float2 g_stats[Bb * Ff];

__device__ __align__(16) __half g_ah[SEQ_ELEMS];      // conv input hi
__device__ __align__(16) __half g_al[SEQ_ELEMS];      // conv input lo * 2048
__device__ __align__(16) __half g_hh[SEQ_ELEMS];      // hidden hi
__device__ __align__(16) __half g_hl[SEQ_ELEMS];      // hidden lo * 2048
__device__ __align__(16) __half g_whi[4][W_ELEMS];    // weights [co][k] hi
__device__ __align__(16) __half g_wlo[4][W_ELEMS];    // weights [co][k] lo * 2048

// ---------------------------------------------------------------------------
// PTX helpers (portable to plain sm_103)
// ---------------------------------------------------------------------------
__device__ __forceinline__ uint32_t smem_u32(const void* p) {
    uint32_t a;
    asm("{ .reg .u64 t; cvta.to.shared.u64 t, %1; cvt.u32.u64 %0, t; }" : "=r"(a) : "l"(p));
    return a;
}
__device__ __forceinline__ void cp16(uint32_t dst, const void* src, uint32_t srcsz) {
    asm volatile("cp.async.cg.shared.global [%0], [%1], 16, %2;"
                 :: "r"(dst), "l"(src), "r"(srcsz) : "memory");
}
#define CP_COMMIT() asm volatile("cp.async.commit_group;" ::: "memory")
#define CP_WAIT0()  asm volatile("cp.async.wait_group 0;" ::: "memory")

__device__ __forceinline__ void ldsm4(uint32_t* r, uint32_t addr) {
    asm volatile("ldmatrix.sync.aligned.m8n8.x4.shared.b16 {%0,%1,%2,%3}, [%4];"
                 : "=r"(r[0]), "=r"(r[1]), "=r"(r[2]), "=r"(r[3]) : "r"(addr));
}
// hi*hi term: fp32 accumulate
__device__ __forceinline__ void mma_f32(float* d, const uint32_t* a, const uint32_t* b)
{
    asm volatile(
        "mma.sync.aligned.m16n8k16.row.col.f32.f16.f16.f32 "
        "{%0,%1,%2,%3}, {%4,%5,%6,%7}, {%8,%9}, {%0,%1,%2,%3};"
        : "+f"(d[0]), "+f"(d[1]), "+f"(d[2]), "+f"(d[3])
        : "r"(a[0]), "r"(a[1]), "r"(a[2]), "r"(a[3]), "r"(b[0]), "r"(b[1]));
}
// cross terms: fp16 accumulate (operands pre-scaled by 2048 keep products normal)
__device__ __forceinline__ void mma_f16(uint32_t* d, const uint32_t* a, const uint32_t* b)
{
    asm volatile(
        "mma.sync.aligned.m16n8k16.row.col.f16.f16.f16.f16 "
        "{%0,%1}, {%2,%3,%4,%5}, {%6,%7}, {%0,%1};"
        : "+r"(d[0]), "+r"(d[1])
        : "r"(a[0]), "r"(a[1]), "r"(a[2]), "r"(a[3]), "r"(b[0]), "r"(b[1]));
}

// ---------------------------------------------------------------------------
// Implicit-GEMM 5x5 SAME conv, 256 -> 1024, fp16 3-term split:
//   out = Ahi*Bhi (f32 acc) + (Ahi*Blo' + Alo'*Bhi) (f16 acc) / 2048
// Template: CM = CTA pixel tile (128 input / 64 recurrent), WM = warps in M.
// 8 warps arranged WM x (8/WM); warp tile = 32 x (WM*8). MF = 2 always.
// Chunk loop: ONE barrier per chunk (wait0 -> sync -> stage(c+1) -> compute),
// A-fragments double-buffered across the 4 k-steps.
// grid = (ceil(Mtot/CM), 16, Z). Z==1: full K + bias. Z==2: split-K halves.
// ---------------------------------------------------------------------------
template <int CM, int WM, int MINB>
__global__ __launch_bounds__(256, MINB) void conv_mma(
    const __half* __restrict__ a_hi, const __half* __restrict__ a_lo,
    size_t a_img_stride,
    const __half* __restrict__ w_hi, const __half* __restrict__ w_lo,
    const float* __restrict__ bias,
    float* __restrict__ out, size_t out_img_stride,
    float* __restrict__ out2, size_t out2_img_stride,
    int Mtot)
{
    constexpr int NF    = WM;            // n-fragments per warp (8-col units)
    constexpr int NPAIR = NF / 2;        // ldmatrix.x4 pairs for B
    constexpr int A_T_B = CM * SROW_B;
    constexpr int ALO   = A_T_B;
    constexpr int BHI   = 2 * A_T_B;
    constexpr int BUF   = 2 * A_T_B + 2 * B_T_B;
    constexpr int TPR   = 256 / CM;      // staging threads per A row
    constexpr int CPQ   = 8 / TPR;       // cp16 per thread per A operand

    extern __shared__ __align__(16) char sm[];
    const uint32_t smb = smem_u32(sm);

    const int tid  = threadIdx.x;
    const int lane = tid & 31;
    const int wid  = tid >> 5;
    const int m0   = blockIdx.x * CM;
    const int co0  = blockIdx.y * NT;

    int cbeg = 0, cend = NCHUNK;
    float* dst = out;
    size_t dstride = out_img_stride;
    bool accum = false;
    const float* bs = bias;
    if (gridDim.z == 2) {
        bs = nullptr;
        if (blockIdx.z == 0) { cend = NCHUNK / 2; accum = true; }
        else { cbeg = NCHUNK / 2; dst = out2; dstride = out2_img_stride; }
    }

    // ---- staging geometry
    const int arow = tid / TPR;
    const int asub = tid % TPR;
    int pc = m0 + arow; if (pc >= Mtot) pc = Mtot - 1;
    const int img = pc / HW;
    const int rm  = pc - img * HW;
    const int py  = rm / Ww;
    const int px  = rm - py * Ww;
    const __half* aimg_hi = a_hi + (size_t)img * a_img_stride;
    const __half* aimg_lo = a_lo + (size_t)img * a_img_stride;

    const int brow = tid >> 2;
    const int bq   = tid & 3;
    const __half* wrow_hi = w_hi + (size_t)(co0 + brow) * KTOT;
    const __half* wrow_lo = w_lo + (size_t)(co0 + brow) * KTOT;

    const uint32_t da0 = smb + arow * SROW_B + asub * (128 / TPR);
    const uint32_t db0 = smb + BHI + brow * SROW_B + (bq << 5);

    auto stage = [&](int c, int buf) {
        const uint32_t bo = (uint32_t)buf * BUF;
        const int tp  = c >> 2;
        const int ci0 = (c & 3) << 6;
        const int dy  = tp / 5;
        const int dx  = tp - dy * 5;
        const int gy  = py + dy - 2;
        const int gx  = px + dx - 2;
        const bool inb = (gy >= 0 && gy < Hh && gx >= 0 && gx < Ww);
        const uint32_t sz = inb ? 16u : 0u;
        const size_t off = inb ?
            ((((size_t)(gy * Ww + gx)) << 8) + ci0 + asub * (64 / TPR)) : 0;
        const char* sh = (const char*)(aimg_hi + off);
        const char* sl = (const char*)(aimg_lo + off);
        const uint32_t da = da0 + bo;
#pragma unroll
        for (int q = 0; q < CPQ; q++) {
            cp16(da + q * 16,       sh + q * 16, sz);
            cp16(da + ALO + q * 16, sl + q * 16, sz);
        }
        const char* wh = (const char*)(wrow_hi + (c << 6) + (bq << 4));
        const char* wl = (const char*)(wrow_lo + (c << 6) + (bq << 4));
        const uint32_t db = db0 + bo;
        cp16(db,      wh,      16);
        cp16(db + 16, wh + 16, 16);
        cp16(db + B_T_B,      wl,      16);
        cp16(db + B_T_B + 16, wl + 16, 16);
    };

    // ---- compute geometry: 8 warps = WM (m) x 8/WM (n); warp tile 32 x NF*8
    const int wm  = wid & (WM - 1);
    const int wn  = wid / WM;
    const int m0w = wm * 32;
    const int n0w = wn * (NF * 8);
    const int g   = lane >> 2;
    const int tk  = (lane & 3) * 2;

    uint32_t abase[2], bbase[NPAIR];
#pragma unroll
    for (int mf = 0; mf < 2; mf++)
        abase[mf] = smb + (m0w + mf * 16 + (lane & 15)) * SROW_B + ((lane & 16) ? 16 : 0);
#pragma unroll
    for (int p = 0; p < NPAIR; p++)
        bbase[p] = smb + BHI + (n0w + p * 16 + (lane & 15)) * SROW_B + ((lane & 16) ? 16 : 0);

    float    accf[2][NF][4];
    uint32_t acch[2][NF][2];
#pragma unroll
    for (int mf = 0; mf < 2; mf++)
#pragma unroll
        for (int nf = 0; nf < NF; nf++) {
#pragma unroll
            for (int r = 0; r < 4; r++) accf[mf][nf][r] = 0.f;
            acch[mf][nf][0] = 0u; acch[mf][nf][1] = 0u;
        }

    // ---- pipeline: one barrier per chunk
    stage(cbeg, 0);
    CP_COMMIT();

    for (int c = cbeg; c < cend; ++c) {
        const int buf = (c - cbeg) & 1;
        CP_WAIT0();            // chunk c landed (own copies)
        __syncthreads();       // all threads' copies visible; all ldsm(c-1) done
        if (c + 1 < cend) {    // overwrite buf of c-1 — safe after the barrier
            stage(c + 1, buf ^ 1);
            CP_COMMIT();
        }

        const uint32_t bo = (uint32_t)buf * BUF;

        // A-fragments double-buffered across k-steps
        uint32_t ah[2][2][4], al[2][2][4];
#pragma unroll
        for (int mf = 0; mf < 2; mf++) {
            ldsm4(ah[0][mf], abase[mf] + bo);
            ldsm4(al[0][mf], abase[mf] + bo + ALO);
        }
#pragma unroll
        for (int ks = 0; ks < 4; ++ks) {
            const int pb = ks & 1;
            if (ks < 3) {
#pragma unroll
                for (int mf = 0; mf < 2; mf++) {
                    ldsm4(ah[pb ^ 1][mf], abase[mf] + bo + (ks + 1) * 32);
                    ldsm4(al[pb ^ 1][mf], abase[mf] + bo + ALO + (ks + 1) * 32);
                }
            }
            uint32_t bh4[NPAIR][4], bl4[NPAIR][4];
#pragma unroll
            for (int p = 0; p < NPAIR; p++) {
                ldsm4(bh4[p], bbase[p] + bo + ks * 32);
                ldsm4(bl4[p], bbase[p] + bo + B_T_B + ks * 32);
            }
            // x4 B layout: r0 = rows 0-7 k0-7, r1 = rows 8-15 k0-7,
            //              r2 = rows 0-7 k8-15, r3 = rows 8-15 k8-15
#pragma unroll
            for (int mf = 0; mf < 2; mf++)
#pragma unroll
                for (int p = 0; p < NPAIR; p++)
#pragma unroll
                    for (int e = 0; e < 2; e++) {
                        uint32_t bh[2] = { bh4[p][e], bh4[p][e + 2] };
                        uint32_t bl[2] = { bl4[p][e], bl4[p][e + 2] };
                        const int nf = p * 2 + e;
                        mma_f32(accf[mf][nf], ah[pb][mf], bh);
                        mma_f16(acch[mf][nf], ah[pb][mf], bl);
                        mma_f16(acch[mf][nf], al[pb][mf], bh);
                    }
        }
    }

    // ---- epilogue: total = accf + acch/2048
#pragma unroll
    for (int mf = 0; mf < 2; mf++) {
        float cr[NF][4];
#pragma unroll
        for (int nf = 0; nf < NF; nf++) {
            const __half2 c01 = *reinterpret_cast<const __half2*>(&acch[mf][nf][0]);
            const __half2 c23 = *reinterpret_cast<const __half2*>(&acch[mf][nf][1]);
            cr[nf][0] = __half2float(c01.x); cr[nf][1] = __half2float(c01.y);
            cr[nf][2] = __half2float(c23.x); cr[nf][3] = __half2float(c23.y);
        }
#pragma unroll
        for (int half = 0; half < 2; half++) {
            const int p = m0 + m0w + mf * 16 + g + half * 8;
            if (p >= Mtot) continue;
            const int im = p / HW;
            const int pp = p - im * HW;
            float* orow = dst + (size_t)im * dstride + (size_t)pp * COUT + co0;
#pragma unroll
            for (int nf = 0; nf < NF; nf++) {
                const int col = n0w + nf * 8 + tk;
                float v0 = accf[mf][nf][half * 2 + 0] + LO_INV * cr[nf][half * 2 + 0];
                float v1 = accf[mf][nf][half * 2 + 1] + LO_INV * cr[nf][half * 2 + 1];
                float2* d2 = (float2*)(orow + col);
                if (accum) {
                    float2 o = *d2;
                    v0 += o.x; v1 += o.y;
                } else if (bs) {
                    v0 += bs[co0 + col];
                    v1 += bs[co0 + col + 1];
                }
                d2->x = v0; d2->y = v1;
            }
        }
    }
}

// ---------------------------------------------------------------------------
// Fused prep: z<4 -> weight transpose + split; z==4 -> x split.
// ---------------------------------------------------------------------------
__global__ void prep(const float* __restrict__ w0, const float* __restrict__ w1,
                     const float* __restrict__ w2, const float* __restrict__ w3,
                     __half* __restrict__ whi, __half* __restrict__ wlo,
                     const float* __restrict__ x,
                     __half* __restrict__ ah, __half* __restrict__ al)
{
    const int z = blockIdx.z;
    if (z < 4) {
        const float* w = (z == 0) ? w0 : (z == 1) ? w1 : (z == 2) ? w2 : w3;
        __half* whiz = whi + (size_t)z * W_ELEMS;
        __half* wloz = wlo + (size_t)z * W_ELEMS;
        __shared__ float tile[32][33];
        const int k0  = blockIdx.x * 32;
        const int co0 = blockIdx.y * 32;
        const int tx = threadIdx.x, ty = threadIdx.y;
#pragma unroll
        for (int i = 0; i < 4; i++)
            tile[ty + i * 8][tx] = w[(size_t)(k0 + ty + i * 8) * COUT + co0 + tx];
        __syncthreads();
#pragma unroll
        for (int i = 0; i < 4; i++) {
            const int co = co0 + ty + i * 8;
            const int k  = k0 + tx;
            const float v = tile[tx][ty + i * 8];
            const __half h = __float2half_rn(v);
            whiz[(size_t)co * KTOT + k] = h;
            wloz[(size_t)co * KTOT + k] = __float2half_rn((v - __half2float(h)) * LO_SCALE);
        }
    } else {
        const int tid = threadIdx.y * 32 + threadIdx.x;
        const size_t base = ((size_t)blockIdx.y * 200 + blockIdx.x) * 256 + tid;
        const size_t stride = (size_t)200 * 32 * 256;
        for (size_t i = base; i < SEQ_ELEMS; i += stride) {
            const float v = x[i];
            const __half h = __float2half_rn(v);
            ah[i] = h;
            al[i] = __float2half_rn((v - __half2float(h)) * LO_SCALE);
        }
    }
}

// ---------------------------------------------------------------------------
// LSTM pointwise (+ emit hidden-state hi/lo); sums split-K partials
// ---------------------------------------------------------------------------
__device__ __forceinline__ float hsig(float x)
{
    return fminf(fmaxf(0.2f * x + 0.5f, 0.f), 1.f);
}

__global__ void lstm_point(const float* __restrict__ xg_t,
                           const float* __restrict__ xg2,
                           float* __restrict__ cbuf,
                           float* __restrict__ h_out,
                           __half* __restrict__ hh,
                           __half* __restrict__ hl,
                           int first)
{
    int idx = blockIdx.x * 256 + threadIdx.x;
    if (idx >= (int)STATE_ELEMS) return;
    int b   = idx / (HW * Ff);
    int rem = idx - b * (HW * Ff);
    int pix = rem >> 8;
    int ch  = rem & 255;
    const float* gp = xg_t + (size_t)b * (Tt * HW * COUT) + (size_t)pix * COUT + ch;
    float gi = gp[0], gf = gp[256], gc = gp[512], go = gp[768];
    if (xg2) {
        const float* g2 = xg2 + ((size_t)b * HW + pix) * COUT + ch;
        gi += g2[0]; gf += g2[256]; gc += g2[512]; go += g2[768];
    }
    float i_ = hsig(gi);
    float f_ = hsig(gf);
    float cc = fmaxf(gc, 0.f);
    float o_ = hsig(go);
    float cp = first ? 0.f : cbuf[idx];
    float cn = f_ * cp + i_ * cc;
    cbuf[idx] = cn;
    float h = o_ * fmaxf(cn, 0.f);
    size_t oidx = (size_t)b * (Tt * HW * Ff) + rem;
    h_out[oidx] = h;
    __half hb = __float2half_rn(h);
    hh[oidx] = hb;
    hl[oidx] = __float2half_rn((h - __half2float(hb)) * LO_SCALE);
}

// ---------------------------------------------------------------------------
// Instance norm
// ---------------------------------------------------------------------------
__global__ void inorm_stats(const float* __restrict__ seq, float2* __restrict__ stats)
{
    int b  = blockIdx.x >> 8;
    int ch = blockIdx.x & 255;
    const float* base = seq + (size_t)b * Tt * HW * Ff + ch;
    float s = 0.f, s2 = 0.f;
    for (int e = threadIdx.x; e < Tt * HW; e += 256) {
        float v = base[(size_t)e * Ff];
        s += v; s2 += v * v;
    }
    __shared__ float rs[256], rq[256];
    rs[threadIdx.x] = s;  rq[threadIdx.x] = s2;
    __syncthreads();
    for (int st = 128; st > 0; st >>= 1) {
        if (threadIdx.x < st) {
            rs[threadIdx.x] += rs[threadIdx.x + st];
            rq[threadIdx.x] += rq[threadIdx.x + st];
        }
        __syncthreads();
    }
    if (threadIdx.x == 0) {
        const float inv = 1.f / (float)(Tt * HW);
        float mu  = rs[0] * inv;
        float var = rq[0] * inv - mu * mu;
        stats[blockIdx.x] = make_float2(mu, rsqrtf(var + 1e-3f));
    }
}

__global__ void inorm_apply(const float* __restrict__ in,
                            const float2* __restrict__ stats,
                            const float* __restrict__ gamma,
                            const float* __restrict__ beta,
                            float* __restrict__ out,
                            __half* __restrict__ sh,
                            __half* __restrict__ sl)
{
    size_t idx = (size_t)blockIdx.x * 256 + threadIdx.x;
    if (idx >= SEQ_ELEMS) return;
    int ch = (int)(idx & 255);
    int b  = (int)(idx / ((size_t)Tt * HW * Ff));
    float2 st = stats[b * 256 + ch];
    float v = gamma[ch] * (in[idx] - st.x) * st.y + beta[ch];
    out[idx] = v;
    if (sh) {
        __half h = __float2half_rn(v);
        sh[idx] = h;
        sl[idx] = __float2half_rn((v - __half2float(h)) * LO_SCALE);
    }
}

__global__ void copy_states(const float* __restrict__ seq2,
                            const float* __restrict__ cbuf,
                            float* __restrict__ h2, float* __restrict__ c2)
{
    int idx = blockIdx.x * 256 + threadIdx.x;
    if (idx >= (int)STATE_ELEMS) return;
    int b   = idx / (HW * Ff);
    int rem = idx - b * (HW * Ff);
    h2[idx] = seq2[(size_t)b * Tt * HW * Ff + (size_t)(Tt - 1) * HW * Ff + rem];
    c2[idx] = cbuf[idx];
}

// ---------------------------------------------------------------------------
// Orchestration
// ---------------------------------------------------------------------------
extern "C" void kernel_launch(void* const* d_in, const int* /*in_sizes*/, int /*n_in*/,
                              void* d_out, int /*out_size*/)
{
    const float* x   = (const float*)d_in[0];
    const float* k1  = (const float*)d_in[1];
    const float* rk1 = (const float*)d_in[2];
    const float* b1  = (const float*)d_in[3];
    const float* g1  = (const float*)d_in[4];
    const float* bt1 = (const float*)d_in[5];
    const float* k2  = (const float*)d_in[6];
    const float* rk2 = (const float*)d_in[7];
    const float* b2  = (const float*)d_in[8];
    const float* g2  = (const float*)d_in[9];
    const float* bt2 = (const float*)d_in[10];

    float* out    = (float*)d_out;
    float* out_h2 = out + SEQ_ELEMS;
    float* out_c2 = out_h2 + STATE_ELEMS;

    float *xg, *xg2, *seq1, *seq2, *cbuf;
    float2* stats;
    __half *ah, *al, *hh, *hl, *whi, *wlo;
    cudaGetSymbolAddress((void**)&xg,    g_xg);
    cudaGetSymbolAddress((void**)&xg2,   g_xg2);
    cudaGetSymbolAddress((void**)&seq1,  g_seq1);
    cudaGetSymbolAddress((void**)&seq2,  g_seq2);
    cudaGetSymbolAddress((void**)&cbuf,  g_c);
    cudaGetSymbolAddress((void**)&stats, g_stats);
    cudaGetSymbolAddress((void**)&ah,    g_ah);
    cudaGetSymbolAddress((void**)&al,    g_al);
    cudaGetSymbolAddress((void**)&hh,    g_hh);
    cudaGetSymbolAddress((void**)&hl,    g_hl);
    cudaGetSymbolAddress((void**)&whi,   g_whi);
    cudaGetSymbolAddress((void**)&wlo,   g_wlo);

    // input conv: CM=128, 4m x 2n warps, 2 CTAs/SM
    constexpr int SMEM_IN  = 2 * (2 * 128 * SROW_B + 2 * B_T_B);   // 110592
    // recurrent conv: CM=64, 2m x 4n warps, 3 CTAs/SM
    constexpr int SMEM_REC = 2 * (2 * 64 * SROW_B + 2 * B_T_B);    // 73728
    cudaFuncSetAttribute((const void*)conv_mma<128, 4, 2>,
                         cudaFuncAttributeMaxDynamicSharedMemorySize, SMEM_IN);
    cudaFuncSetAttribute((const void*)conv_mma<64, 2, 3>,
                         cudaFuncAttributeMaxDynamicSharedMemorySize, SMEM_REC);

    // single fused prep launch (weights z=0..3, x split z=4)
    prep<<<dim3(KTOT / 32, COUT / 32, 5), dim3(32, 8)>>>(
        k1, rk1, k2, rk2, whi, wlo, x, ah, al);

    const int Min  = Bb * Tt * HW;                      // 21504
    const int Mrec = Bb * HW;                           // 1344
    const dim3 igrid(Min / 128, COUT / NT, 1);          // (168, 16, 1)
    const dim3 rgrid(Mrec / 64, COUT / NT, 2);          // (21, 16, 2)
    const int pblocks = (int)((STATE_ELEMS + 255) / 256);
    const int sblocks = (int)((SEQ_ELEMS + 255) / 256);
    const size_t XSTR  = (size_t)Tt * HW * COUT;
    const size_t X2STR = (size_t)HW * COUT;
    const size_t HSTR  = (size_t)Tt * HW * Ff;

    // ---------------- Layer 1 ----------------
    conv_mma<128, 4, 2><<<igrid, 256, SMEM_IN>>>(
        ah, al, (size_t)HW * CIN, whi + 0 * W_ELEMS, wlo + 0 * W_ELEMS,
        b1, xg, (size_t)HW * COUT, nullptr, 0, Min);

    for (int t = 0; t < Tt; ++t) {
        if (t > 0)
            conv_mma<64, 2, 3><<<rgrid, 256, SMEM_REC>>>(
                hh + (size_t)(t - 1) * HW * Ff, hl + (size_t)(t - 1) * HW * Ff, HSTR,
                whi + 1 * W_ELEMS, wlo + 1 * W_ELEMS, nullptr,
                xg + (size_t)t * HW * COUT, XSTR, xg2, X2STR, Mrec);
        lstm_point<<<pblocks, 256>>>(xg + (size_t)t * HW * COUT,
                                     (t > 0) ? xg2 : nullptr, cbuf,
                                     seq1 + (size_t)t * HW * Ff,
                                     hh + (size_t)t * HW * Ff,
                                     hl + (size_t)t * HW * Ff, t == 0);
    }
    inorm_stats<<<Bb * Ff, 256>>>(seq1, stats);
    inorm_apply<<<sblocks, 256>>>(seq1, stats, g1, bt1, seq1, ah, al);

    // ---------------- Layer 2 ----------------
    conv_mma<128, 4, 2><<<igrid, 256, SMEM_IN>>>(
        ah, al, (size_t)HW * CIN, whi + 2 * W_ELEMS, wlo + 2 * W_ELEMS,
        b2, xg, (size_t)HW * COUT, nullptr, 0, Min);

    for (int t = 0; t < Tt; ++t) {
        if (t > 0)
            conv_mma<64, 2, 3><<<rgrid, 256, SMEM_REC>>>(
                hh + (size_t)(t - 1) * HW * Ff, hl + (size_t)(t - 1) * HW * Ff, HSTR,
                whi + 3 * W_ELEMS, wlo + 3 * W_ELEMS, nullptr,
                xg + (size_t)t * HW * COUT, XSTR, xg2, X2STR, Mrec);
        lstm_point<<<pblocks, 256>>>(xg + (size_t)t * HW * COUT,
                                     (t > 0) ? xg2 : nullptr, cbuf,
                                     seq2 + (size_t)t * HW * Ff,
                                     hh + (size_t)t * HW * Ff,
                                     hl + (size_t)t * HW * Ff, t == 0);
    }

    copy_states<<<pblocks, 256>>>(seq2, cbuf, out_h2, out_c2);
    inorm_stats<<<Bb * Ff, 256>>>(seq2, stats);
    inorm_apply<<<sblocks, 256>>>(seq2, stats, g2, bt2, out, nullptr, nullptr);
}